// round 14
// baseline (speedup 1.0000x reference)
#include <cuda_runtime.h>

#define H_ 4
#define D_ 64
#define L_ 7
#define VOCAB_ 6
#define NOUT_ 11
#define BATCH_ 32768
#define EPS_ 1e-5f

using u64 = unsigned long long;

__device__ __forceinline__ u64 pk2(float x, float y) {
    u64 r; asm("mov.b64 %0, {%1, %2};" : "=l"(r) : "f"(x), "f"(y)); return r;
}
__device__ __forceinline__ void fma2(u64& a, u64 x, u64 w) {
    asm("fma.rn.f32x2 %0, %1, %2, %0;" : "+l"(a) : "l"(x), "l"(w));
}
__device__ __forceinline__ float2 up2(u64 v) {
    float2 r; asm("mov.b64 {%0, %1}, %2;" : "=f"(r.x), "=f"(r.y) : "l"(v)); return r;
}

// ---------------- device scratch ----------------
__device__ float g_Q[168 * D_];
__device__ float g_K[168 * D_];
__device__ float g_V[168 * D_];
__device__ float g_Wd[D_ * D_];
__device__ float g_E[H_ * L_ * VOCAB_ * L_ * VOCAB_]; // [h][k][tk][q][tq] (LDG)
__device__ float g_VW[H_ * L_ * VOCAB_ * D_];         // [jt][64]
__device__ float g_P[168 * 128];                      // [jt][128] = VW[jt] @ (g1*C1)
__device__ float g_A[128];
__device__ float g_B[128];
__device__ float g_Cc[128];
__device__ float g_Wft[NOUT_ * D_];
__device__ float g_bf[NOUT_];
__device__ float g_C2p[64 * 128];                     // [kk][c][2]

// ---------------- prep stage 1: T (recomputed per CTA) -> Q/K/V slices ----------------
// grid 48 = 12 (which x head) x 4 row-slices, block 256
__global__ void kP1(const float* __restrict__ emb, const float* __restrict__ pos,
                    const float* __restrict__ in_w, const float* __restrict__ in_b,
                    const float* __restrict__ e_wq, const float* __restrict__ e_wk,
                    const float* __restrict__ e_wv) {
    __shared__ float sT[11 * 64];
    int tid = threadIdx.x;
    int combo = blockIdx.x >> 2, s = blockIdx.x & 3;
    int which = combo >> 2, h = combo & 3;
    int r0 = s * 11;
    int nr = (42 - r0) < 11 ? (42 - r0) : 11;

    for (int i = tid; i < nr * 64; i += 256) {
        int lvl = i >> 6, e = i & 63;
        int lv = r0 + lvl;
        int l = lv / 6, v = lv % 6;
        float acc = in_b[e];
        #pragma unroll 8
        for (int d = 0; d < 64; d++) acc = fmaf(emb[v * 64 + d], in_w[d * 64 + e], acc);
        acc = fmaf(pos[l], in_w[64 * 64 + e], acc);
        sT[i] = acc;
    }
    __syncthreads();

    const float* w = (which == 0) ? e_wq : (which == 1) ? e_wk : e_wv;
    float* outg = (which == 0) ? g_Q : (which == 1) ? g_K : g_V;
    for (int i = tid; i < nr * 64; i += 256) {
        int lvl = i >> 6, e = i & 63;
        float acc = 0.f;
        #pragma unroll 8
        for (int d = 0; d < 64; d++) acc = fmaf(sT[lvl * 64 + d], w[(h * 64 + d) * 64 + e], acc);
        outg[(h * 42 + r0 + lvl) * 64 + e] = acc;
    }
}

// ---------------- prep stage 2: E (28 slices), VW (8 slices), Wd (16 slices) ----------------
// grid 52, block 256
__global__ void kP2(const float* __restrict__ e_wo,
                    const float* __restrict__ d_wv, const float* __restrict__ d_wo) {
    int tid = threadIdx.x;
    int cta = blockIdx.x;

    if (cta < 28) {
        int h = cta / 7, seg = cta % 7;
        for (int i = seg * 252 + tid; i < (seg + 1) * 252; i += 256) {
            int r = i;
            int tq = r % 6; r /= 6;
            int q  = r % 7; r /= 7;
            int tk = r % 6; r /= 6;
            int k  = r;
            const float* Q = g_Q + ((h * 7 + q) * 6 + tq) * 64;
            const float* K = g_K + ((h * 7 + k) * 6 + tk) * 64;
            float s = 0.f;
            #pragma unroll 8
            for (int d = 0; d < 64; d++) s = fmaf(Q[d], K[d], s);
            g_E[h * 1764 + i] = __expf(s * 0.125f);
        }
    } else if (cta < 36) {
        int idx = cta - 28;
        for (int i = tid; i < 21 * 64; i += 256) {
            int rl = i >> 6, e = i & 63;
            int row = idx * 21 + rl;
            int h = row / 42;
            float acc = 0.f;
            #pragma unroll 8
            for (int d = 0; d < 64; d++) acc = fmaf(g_V[row * 64 + d], e_wo[(h * 64 + d) * 64 + e], acc);
            g_VW[row * 64 + e] = acc;
        }
    } else {
        int idx = cta - 36;            // 16 CTAs x 4 r-rows
        int r = idx * 4 + (tid >> 6);
        int j = tid & 63;
        float acc = 0.f;
        for (int hh = 0; hh < 4; hh++)
            #pragma unroll 8
            for (int d = 0; d < 64; d++)
                acc = fmaf(d_wv[(hh * 64 + r) * 64 + d], d_wo[(hh * 64 + d) * 64 + j], acc);
        g_Wd[r * 64 + j] = acc;
    }
}

// ---------------- prep stage 3: P (16 slices), A/B/Cc, Wf/bf/C2p ----------------
// grid 18, block 256
__global__ void kP3(const float* __restrict__ g1, const float* __restrict__ b1,
                    const float* __restrict__ c1w, const float* __restrict__ c1b,
                    const float* __restrict__ e_bo,
                    const float* __restrict__ d_bo,
                    const float* __restrict__ fc_w, const float* __restrict__ fc_b,
                    const float* __restrict__ c2w) {
    __shared__ float sG[64 * 128];
    int tid = threadIdx.x;
    int cta = blockIdx.x;

    if (cta < 17) {
        for (int i = tid; i < 64 * 128; i += 256) {
            int d = i >> 7;
            sG[i] = g1[d] * c1w[i];
        }
        __syncthreads();
    }

    if (cta < 16) {
        for (int i = cta * 1344 + tid; i < (cta + 1) * 1344; i += 256) {
            int row = i >> 7, c = i & 127;
            const float* vw = g_VW + row * 64;
            float acc = 0.f;
            #pragma unroll 8
            for (int d = 0; d < 64; d++) acc = fmaf(vw[d], sG[d * 128 + c], acc);
            g_P[i] = acc;
        }
    } else if (cta == 16) {
        for (int c = tid; c < 128; c += 256) {
            float a = 0.f, b = c1b[c], cc = 0.f;
            #pragma unroll 8
            for (int d = 0; d < 64; d++) {
                float g = sG[d * 128 + c];
                a += g;
                b = fmaf(b1[d], c1w[d * 128 + c], b);
                cc = fmaf(e_bo[d], g, cc);
            }
            g_A[c] = a; g_B[c] = b; g_Cc[c] = cc;
        }
    } else {
        // Wft [n][64]
        for (int i = tid; i < NOUT_ * 64; i += 256) {
            int n = i >> 6, d = i & 63;
            float acc = 0.f;
            #pragma unroll 8
            for (int j = 0; j < 64; j++) acc = fmaf(g_Wd[d * 64 + j], fc_w[j * NOUT_ + n], acc);
            g_Wft[i] = acc;
        }
        if (tid < NOUT_) {
            float b = fc_b[tid];
            #pragma unroll 8
            for (int j = 0; j < 64; j++) b = fmaf(d_bo[j], fc_w[j * NOUT_ + tid], b);
            g_bf[tid] = b;
        }
        for (int i = tid; i < 64 * 128; i += 256) {
            int kk = i >> 7, r = i & 127;
            int c = r >> 1, j = r & 1;
            g_C2p[i] = c2w[(2 * kk + j) * 64 + c];
        }
    }
}

// ---------------- main fused kernel (unchanged from R13) ----------------
#define NWARP 15
#define NTHR  (NWARP * 32)
#define PWSC  1120
#define SMEM_FLOATS (40848 + NWARP * PWSC)

__global__ __launch_bounds__(NTHR, 1)
void k_main(const int* __restrict__ tokens,
            const float* __restrict__ e_bo,
            const float* __restrict__ g1, const float* __restrict__ b1,
            const float* __restrict__ c2b,
            const float* __restrict__ g2, const float* __restrict__ b2,
            float* __restrict__ out, int totalWarps) {
    extern __shared__ float sm[];
    float* sP   = sm;                 // 21504
    float* sVW  = sP + 21504;         // 10752
    float* sC2  = sVW + 10752;        // 8192
    float* sA   = sC2 + 8192;         // 128
    float* sB   = sA + 128;           // 128
    float* sCc  = sB + 128;           // 128
    float* sBf  = sCc + 128;          // 16
    float* sPW  = sBf + 16;

    int tid = threadIdx.x;
    for (int i = tid; i < 21504 / 4; i += NTHR) ((float4*)sP)[i]  = ((const float4*)g_P)[i];
    for (int i = tid; i < 10752 / 4; i += NTHR) ((float4*)sVW)[i] = ((const float4*)g_VW)[i];
    for (int i = tid; i < 8192 / 4;  i += NTHR) ((float4*)sC2)[i] = ((const float4*)g_C2p)[i];
    for (int i = tid; i < 128 / 4;   i += NTHR) {
        ((float4*)sA)[i]  = ((const float4*)g_A)[i];
        ((float4*)sB)[i]  = ((const float4*)g_B)[i];
        ((float4*)sCc)[i] = ((const float4*)g_Cc)[i];
    }
    if (tid < NOUT_) sBf[tid] = g_bf[tid];
    __syncthreads();

    int lane = tid & 31, wid = tid >> 5;

    float2 bo2  = ((const float2*)e_bo)[lane];
    float2 g1v  = ((const float2*)g1)[lane];
    float2 b1v  = ((const float2*)b1)[lane];
    float2 g2v  = ((const float2*)g2)[lane];
    float2 b2v  = ((const float2*)b2)[lane];
    float2 c2b2 = ((const float2*)c2b)[lane];
    u64 c2bp0 = pk2(c2b2.x, 0.f), c2bp1 = pk2(c2b2.y, 0.f);

    float* wcoW = sPW + wid * PWSC;   // [j][8]
    float* h1W  = wcoW + 224;         // 7 rows of 128

    float4 A4  = ((const float4*)sA)[lane];
    float4 B4  = ((const float4*)sB)[lane];
    float4 C4  = ((const float4*)sCc)[lane];

    const float* pC2 = sC2 + 4 * lane;

    int gw = blockIdx.x * NWARP + wid;
    for (int e = gw; e < BATCH_; e += totalWarps) {
        int myTok = 0;
        if (lane < 7) myTok = tokens[e * 7 + lane];
        int t[7];
        #pragma unroll
        for (int i = 0; i < 7; i++) t[i] = __shfl_sync(0xffffffffu, myTok, i);

        if (lane < 28) {
            int k = lane % 7;
            const float* eb = g_E + (lane * 6 + t[k]) * 42;
            float myw[7];
            float den = 0.f;
            #pragma unroll
            for (int q = 0; q < 7; q++) { float x = __ldg(eb + q * 6 + t[q]); myw[q] = x; den += x; }
            float inv = __fdividef(1.f, den);
            float4 wA = make_float4(myw[0] * inv, myw[1] * inv, myw[2] * inv, myw[3] * inv);
            float4 wB = make_float4(myw[4] * inv, myw[5] * inv, myw[6] * inv, 0.f);
            ((float4*)(wcoW + lane * 8))[0] = wA;
            ((float4*)(wcoW + lane * 8))[1] = wB;
        }
        __syncwarp();

        float2 y[7];
        float S[7][4];
        #pragma unroll
        for (int q = 0; q < 7; q++) {
            y[q] = bo2;
            S[q][0] = S[q][1] = S[q][2] = S[q][3] = 0.f;
        }
        #pragma unroll
        for (int j = 0; j < 28; j++) {
            int row = j * 6 + t[j % 7];
            float2 v  = ((const float2*)(sVW + row * 64))[lane];
            float4 pv = ((const float4*)(sP + row * 128))[lane];
            float4 wA = ((const float4*)(wcoW + j * 8))[0];
            float4 wB = ((const float4*)(wcoW + j * 8))[1];
            y[0].x = fmaf(wA.x, v.x, y[0].x); y[0].y = fmaf(wA.x, v.y, y[0].y);
            y[1].x = fmaf(wA.y, v.x, y[1].x); y[1].y = fmaf(wA.y, v.y, y[1].y);
            y[2].x = fmaf(wA.z, v.x, y[2].x); y[2].y = fmaf(wA.z, v.y, y[2].y);
            y[3].x = fmaf(wA.w, v.x, y[3].x); y[3].y = fmaf(wA.w, v.y, y[3].y);
            y[4].x = fmaf(wB.x, v.x, y[4].x); y[4].y = fmaf(wB.x, v.y, y[4].y);
            y[5].x = fmaf(wB.y, v.x, y[5].x); y[5].y = fmaf(wB.y, v.y, y[5].y);
            y[6].x = fmaf(wB.z, v.x, y[6].x); y[6].y = fmaf(wB.z, v.y, y[6].y);
            S[0][0] = fmaf(wA.x, pv.x, S[0][0]); S[0][1] = fmaf(wA.x, pv.y, S[0][1]);
            S[0][2] = fmaf(wA.x, pv.z, S[0][2]); S[0][3] = fmaf(wA.x, pv.w, S[0][3]);
            S[1][0] = fmaf(wA.y, pv.x, S[1][0]); S[1][1] = fmaf(wA.y, pv.y, S[1][1]);
            S[1][2] = fmaf(wA.y, pv.z, S[1][2]); S[1][3] = fmaf(wA.y, pv.w, S[1][3]);
            S[2][0] = fmaf(wA.z, pv.x, S[2][0]); S[2][1] = fmaf(wA.z, pv.y, S[2][1]);
            S[2][2] = fmaf(wA.z, pv.z, S[2][2]); S[2][3] = fmaf(wA.z, pv.w, S[2][3]);
            S[3][0] = fmaf(wA.w, pv.x, S[3][0]); S[3][1] = fmaf(wA.w, pv.y, S[3][1]);
            S[3][2] = fmaf(wA.w, pv.z, S[3][2]); S[3][3] = fmaf(wA.w, pv.w, S[3][3]);
            S[4][0] = fmaf(wB.x, pv.x, S[4][0]); S[4][1] = fmaf(wB.x, pv.y, S[4][1]);
            S[4][2] = fmaf(wB.x, pv.z, S[4][2]); S[4][3] = fmaf(wB.x, pv.w, S[4][3]);
            S[5][0] = fmaf(wB.y, pv.x, S[5][0]); S[5][1] = fmaf(wB.y, pv.y, S[5][1]);
            S[5][2] = fmaf(wB.y, pv.z, S[5][2]); S[5][3] = fmaf(wB.y, pv.w, S[5][3]);
            S[6][0] = fmaf(wB.z, pv.x, S[6][0]); S[6][1] = fmaf(wB.z, pv.y, S[6][1]);
            S[6][2] = fmaf(wB.z, pv.z, S[6][2]); S[6][3] = fmaf(wB.z, pv.w, S[6][3]);
        }

        float mu[7], rs[7];
        {
            float s1[7], ss1[7];
            #pragma unroll
            for (int q = 0; q < 7; q++) {
                s1[q]  = y[q].x + y[q].y;
                ss1[q] = y[q].x * y[q].x + y[q].y * y[q].y;
            }
            #pragma unroll
            for (int o = 16; o > 0; o >>= 1) {
                #pragma unroll
                for (int q = 0; q < 7; q++) {
                    s1[q]  += __shfl_xor_sync(0xffffffffu, s1[q], o);
                    ss1[q] += __shfl_xor_sync(0xffffffffu, ss1[q], o);
                }
            }
            #pragma unroll
            for (int q = 0; q < 7; q++) {
                mu[q] = s1[q] * (1.f / 64.f);
                float var = ss1[q] * (1.f / 64.f) - mu[q] * mu[q];
                rs[q] = rsqrtf(var + EPS_);
            }
        }

        #pragma unroll
        for (int q = 0; q < 7; q++) {
            float4 hv;
            hv.x = fmaf(rs[q], C4.x + S[q][0] - mu[q] * A4.x, B4.x);
            hv.y = fmaf(rs[q], C4.y + S[q][1] - mu[q] * A4.y, B4.y);
            hv.z = fmaf(rs[q], C4.z + S[q][2] - mu[q] * A4.z, B4.z);
            hv.w = fmaf(rs[q], C4.w + S[q][3] - mu[q] * A4.w, B4.w);
            hv.x = fmaxf(hv.x, 0.f); hv.y = fmaxf(hv.y, 0.f);
            hv.z = fmaxf(hv.z, 0.f); hv.w = fmaxf(hv.w, 0.f);
            ((float4*)(h1W + q * 128))[lane] = hv;
        }
        __syncwarp();

        u64 ac0[7], ac1[7];
        #pragma unroll
        for (int i = 0; i < 7; i++) { ac0[i] = c2bp0; ac1[i] = c2bp1; }
        #pragma unroll 2
        for (int kk2 = 0; kk2 < 32; kk2++) {
            ulonglong2 wa = *(const ulonglong2*)(pC2 + (2 * kk2) * 128);
            ulonglong2 wb = *(const ulonglong2*)(pC2 + (2 * kk2 + 1) * 128);
            #pragma unroll
            for (int i = 0; i < 7; i++) {
                ulonglong2 hp = ((const ulonglong2*)(h1W + i * 128))[kk2];
                fma2(ac0[i], hp.x, wa.x); fma2(ac1[i], hp.x, wa.y);
                fma2(ac0[i], hp.y, wb.x); fma2(ac1[i], hp.y, wb.y);
            }
        }

        float2 xs = make_float2(0.f, 0.f);
        {
            float s2[7], ss2[7];
            float2 z[7];
            #pragma unroll
            for (int i = 0; i < 7; i++) {
                float2 f0 = up2(ac0[i]);
                float2 f1 = up2(ac1[i]);
                float xnx = (y[i].x - mu[i]) * rs[i] * g1v.x + b1v.x;
                float xny = (y[i].y - mu[i]) * rs[i] * g1v.y + b1v.y;
                float zx = xnx + fmaxf(f0.x + f0.y, 0.f);
                float zy = xny + fmaxf(f1.x + f1.y, 0.f);
                z[i] = make_float2(zx, zy);
                s2[i] = zx + zy;
                ss2[i] = zx * zx + zy * zy;
            }
            #pragma unroll
            for (int o = 16; o > 0; o >>= 1) {
                #pragma unroll
                for (int i = 0; i < 7; i++) {
                    s2[i]  += __shfl_xor_sync(0xffffffffu, s2[i], o);
                    ss2[i] += __shfl_xor_sync(0xffffffffu, ss2[i], o);
                }
            }
            #pragma unroll
            for (int i = 0; i < 7; i++) {
                float mean = s2[i] * (1.f / 64.f);
                float var  = ss2[i] * (1.f / 64.f) - mean * mean;
                float rstd = rsqrtf(var + EPS_);
                xs.x += (z[i].x - mean) * rstd * g2v.x + b2v.x;
                xs.y += (z[i].y - mean) * rstd * g2v.y + b2v.y;
            }
        }
        __syncwarp();

        ((float2*)h1W)[lane] = xs;
        __syncwarp();
        if (lane < NOUT_) {
            const float4* wrow = (const float4*)(g_Wft + lane * 64);
            float o = sBf[lane];
            #pragma unroll
            for (int d4 = 0; d4 < 16; d4++) {
                float4 xv = ((const float4*)h1W)[d4];
                float4 wv = __ldg(wrow + d4);
                o = fmaf(xv.x, wv.x, o); o = fmaf(xv.y, wv.y, o);
                o = fmaf(xv.z, wv.z, o); o = fmaf(xv.w, wv.w, o);
            }
            out[e * NOUT_ + lane] = o;
        }
        __syncwarp();
    }
}

extern "C" void kernel_launch(void* const* d_in, const int* in_sizes, int n_in,
                              void* d_out, int out_size) {
    const int*   tokens = (const int*)d_in[0];
    const float* emb    = (const float*)d_in[1];
    const float* pos    = (const float*)d_in[2];
    // d_in[3] qparam unused (decoder softmax over singleton q axis == 1)
    const float* in_w   = (const float*)d_in[4];
    const float* in_b   = (const float*)d_in[5];
    const float* e_wq   = (const float*)d_in[6];
    const float* e_wk   = (const float*)d_in[7];
    const float* e_wv   = (const float*)d_in[8];
    const float* e_wo   = (const float*)d_in[9];
    const float* e_bo   = (const float*)d_in[10];
    const float* e_g1   = (const float*)d_in[11];
    const float* e_b1   = (const float*)d_in[12];
    const float* e_c1w  = (const float*)d_in[13];
    const float* e_c1b  = (const float*)d_in[14];
    const float* e_c2w  = (const float*)d_in[15];
    const float* e_c2b  = (const float*)d_in[16];
    const float* e_g2   = (const float*)d_in[17];
    const float* e_b2   = (const float*)d_in[18];
    // d_in[19] d_wq, d_in[20] d_wk unused
    const float* d_wv   = (const float*)d_in[21];
    const float* d_wo   = (const float*)d_in[22];
    const float* d_bo   = (const float*)d_in[23];
    const float* fc_w   = (const float*)d_in[24];
    const float* fc_b   = (const float*)d_in[25];
    float* out = (float*)d_out;

    kP1<<<48, 256>>>(emb, pos, in_w, in_b, e_wq, e_wk, e_wv);
    kP2<<<52, 256>>>(e_wo, d_wv, d_wo);
    kP3<<<18, 256>>>(e_g1, e_b1, e_c1w, e_c1b, e_bo, d_bo, fc_w, fc_b, e_c2w);

    int dev = 0;
    cudaGetDevice(&dev);
    int smCount = 148;
    cudaDeviceGetAttribute(&smCount, cudaDevAttrMultiProcessorCount, dev);

    size_t smemBytes = SMEM_FLOATS * sizeof(float);
    cudaFuncSetAttribute(k_main, cudaFuncAttributeMaxDynamicSharedMemorySize, (int)smemBytes);
    k_main<<<smCount, NTHR, smemBytes>>>(tokens, e_bo, e_g1, e_b1, e_c2b,
                                         e_g2, e_b2, out, smCount * NWARP);
}

// round 15
// speedup vs baseline: 1.5583x; 1.5583x over previous
#include <cuda_runtime.h>

#define H_ 4
#define D_ 64
#define L_ 7
#define VOCAB_ 6
#define NOUT_ 11
#define BATCH_ 32768
#define EPS_ 1e-5f

using u64 = unsigned long long;

__device__ __forceinline__ u64 pk2(float x, float y) {
    u64 r; asm("mov.b64 %0, {%1, %2};" : "=l"(r) : "f"(x), "f"(y)); return r;
}
__device__ __forceinline__ void fma2(u64& a, u64 x, u64 w) {
    asm("fma.rn.f32x2 %0, %1, %2, %0;" : "+l"(a) : "l"(x), "l"(w));
}
__device__ __forceinline__ float2 up2(u64 v) {
    float2 r; asm("mov.b64 {%0, %1}, %2;" : "=f"(r.x), "=f"(r.y) : "l"(v)); return r;
}

// ---------------- device scratch ----------------
__device__ float g_Q[168 * D_];
__device__ float g_K[168 * D_];
__device__ float g_V[168 * D_];
__device__ float g_Wd[D_ * D_];
__device__ float g_E[H_ * L_ * VOCAB_ * L_ * VOCAB_]; // [h][k][tk][q][tq] (LDG)
__device__ float g_VW[H_ * L_ * VOCAB_ * D_];         // [jt][64]
__device__ float g_P[168 * 128];                      // [jt][128] = VW[jt] @ (g1*C1)
__device__ float g_A[128];
__device__ float g_B[128];
__device__ float g_Cc[128];
__device__ float g_Wft[NOUT_ * D_];
__device__ float g_bf[NOUT_];
__device__ float g_C2p[64 * 128];                     // [kk][c][2]

// ---------------- prep stage 1: T (recomputed per CTA) -> Q/K/V slices ----------------
__global__ void kP1(const float* __restrict__ emb, const float* __restrict__ pos,
                    const float* __restrict__ in_w, const float* __restrict__ in_b,
                    const float* __restrict__ e_wq, const float* __restrict__ e_wk,
                    const float* __restrict__ e_wv) {
    __shared__ float sT[11 * 64];
    int tid = threadIdx.x;
    int combo = blockIdx.x >> 2, s = blockIdx.x & 3;
    int which = combo >> 2, h = combo & 3;
    int r0 = s * 11;
    int nr = (42 - r0) < 11 ? (42 - r0) : 11;

    for (int i = tid; i < nr * 64; i += 256) {
        int lvl = i >> 6, e = i & 63;
        int lv = r0 + lvl;
        int l = lv / 6, v = lv % 6;
        float acc = in_b[e];
        #pragma unroll 8
        for (int d = 0; d < 64; d++) acc = fmaf(emb[v * 64 + d], in_w[d * 64 + e], acc);
        acc = fmaf(pos[l], in_w[64 * 64 + e], acc);
        sT[i] = acc;
    }
    __syncthreads();

    const float* w = (which == 0) ? e_wq : (which == 1) ? e_wk : e_wv;
    float* outg = (which == 0) ? g_Q : (which == 1) ? g_K : g_V;
    for (int i = tid; i < nr * 64; i += 256) {
        int lvl = i >> 6, e = i & 63;
        float acc = 0.f;
        #pragma unroll 8
        for (int d = 0; d < 64; d++) acc = fmaf(sT[lvl * 64 + d], w[(h * 64 + d) * 64 + e], acc);
        outg[(h * 42 + r0 + lvl) * 64 + e] = acc;
    }
}

// ---------------- prep stage 2: E (28 slices), VW (8 slices), Wd (16 slices) ----------------
__global__ void kP2(const float* __restrict__ e_wo,
                    const float* __restrict__ d_wv, const float* __restrict__ d_wo) {
    int tid = threadIdx.x;
    int cta = blockIdx.x;

    if (cta < 28) {
        int h = cta / 7, seg = cta % 7;
        for (int i = seg * 252 + tid; i < (seg + 1) * 252; i += 256) {
            int r = i;
            int tq = r % 6; r /= 6;
            int q  = r % 7; r /= 7;
            int tk = r % 6; r /= 6;
            int k  = r;
            const float* Q = g_Q + ((h * 7 + q) * 6 + tq) * 64;
            const float* K = g_K + ((h * 7 + k) * 6 + tk) * 64;
            float s = 0.f;
            #pragma unroll 8
            for (int d = 0; d < 64; d++) s = fmaf(Q[d], K[d], s);
            g_E[h * 1764 + i] = __expf(s * 0.125f);
        }
    } else if (cta < 36) {
        int idx = cta - 28;
        for (int i = tid; i < 21 * 64; i += 256) {
            int rl = i >> 6, e = i & 63;
            int row = idx * 21 + rl;
            int h = row / 42;
            float acc = 0.f;
            #pragma unroll 8
            for (int d = 0; d < 64; d++) acc = fmaf(g_V[row * 64 + d], e_wo[(h * 64 + d) * 64 + e], acc);
            g_VW[row * 64 + e] = acc;
        }
    } else {
        int idx = cta - 36;
        int r = idx * 4 + (tid >> 6);
        int j = tid & 63;
        float acc = 0.f;
        for (int hh = 0; hh < 4; hh++)
            #pragma unroll 8
            for (int d = 0; d < 64; d++)
                acc = fmaf(d_wv[(hh * 64 + r) * 64 + d], d_wo[(hh * 64 + d) * 64 + j], acc);
        g_Wd[r * 64 + j] = acc;
    }
}

// ---------------- prep stage 3: P (16 slices), A/B/Cc, Wf/bf/C2p ----------------
__global__ void kP3(const float* __restrict__ g1, const float* __restrict__ b1,
                    const float* __restrict__ c1w, const float* __restrict__ c1b,
                    const float* __restrict__ e_bo,
                    const float* __restrict__ d_bo,
                    const float* __restrict__ fc_w, const float* __restrict__ fc_b,
                    const float* __restrict__ c2w) {
    __shared__ float sG[64 * 128];
    int tid = threadIdx.x;
    int cta = blockIdx.x;

    if (cta < 17) {
        for (int i = tid; i < 64 * 128; i += 256) {
            int d = i >> 7;
            sG[i] = g1[d] * c1w[i];
        }
        __syncthreads();
    }

    if (cta < 16) {
        for (int i = cta * 1344 + tid; i < (cta + 1) * 1344; i += 256) {
            int row = i >> 7, c = i & 127;
            const float* vw = g_VW + row * 64;
            float acc = 0.f;
            #pragma unroll 8
            for (int d = 0; d < 64; d++) acc = fmaf(vw[d], sG[d * 128 + c], acc);
            g_P[i] = acc;
        }
    } else if (cta == 16) {
        for (int c = tid; c < 128; c += 256) {
            float a = 0.f, b = c1b[c], cc = 0.f;
            #pragma unroll 8
            for (int d = 0; d < 64; d++) {
                float g = sG[d * 128 + c];
                a += g;
                b = fmaf(b1[d], c1w[d * 128 + c], b);
                cc = fmaf(e_bo[d], g, cc);
            }
            g_A[c] = a; g_B[c] = b; g_Cc[c] = cc;
        }
    } else {
        for (int i = tid; i < NOUT_ * 64; i += 256) {
            int n = i >> 6, d = i & 63;
            float acc = 0.f;
            #pragma unroll 8
            for (int j = 0; j < 64; j++) acc = fmaf(g_Wd[d * 64 + j], fc_w[j * NOUT_ + n], acc);
            g_Wft[i] = acc;
        }
        if (tid < NOUT_) {
            float b = fc_b[tid];
            #pragma unroll 8
            for (int j = 0; j < 64; j++) b = fmaf(d_bo[j], fc_w[j * NOUT_ + tid], b);
            g_bf[tid] = b;
        }
        for (int i = tid; i < 64 * 128; i += 256) {
            int kk = i >> 7, r = i & 127;
            int c = r >> 1, j = r & 1;
            g_C2p[i] = c2w[(2 * kk + j) * 64 + c];
        }
    }
}

// ---------------- main fused kernel ----------------
// 14 warps/CTA (reg cap 146 — headroom above ~130 live regs, no spill risk)
#define NWARP 14
#define NTHR  (NWARP * 32)
#define PWSC  1120
#define SMEM_FLOATS (40848 + NWARP * PWSC)

__global__ __launch_bounds__(NTHR, 1)
void k_main(const int* __restrict__ tokens,
            const float* __restrict__ e_bo,
            const float* __restrict__ g1, const float* __restrict__ b1,
            const float* __restrict__ c2b,
            const float* __restrict__ g2, const float* __restrict__ b2,
            float* __restrict__ out, int totalWarps) {
    extern __shared__ float sm[];
    float* sP   = sm;                 // 21504
    float* sVW  = sP + 21504;         // 10752
    float* sC2  = sVW + 10752;        // 8192
    float* sA   = sC2 + 8192;         // 128
    float* sB   = sA + 128;           // 128
    float* sCc  = sB + 128;           // 128
    float* sBf  = sCc + 128;          // 16
    float* sPW  = sBf + 16;

    int tid = threadIdx.x;
    for (int i = tid; i < 21504 / 4; i += NTHR) ((float4*)sP)[i]  = ((const float4*)g_P)[i];
    for (int i = tid; i < 10752 / 4; i += NTHR) ((float4*)sVW)[i] = ((const float4*)g_VW)[i];
    for (int i = tid; i < 8192 / 4;  i += NTHR) ((float4*)sC2)[i] = ((const float4*)g_C2p)[i];
    for (int i = tid; i < 128 / 4;   i += NTHR) {
        ((float4*)sA)[i]  = ((const float4*)g_A)[i];
        ((float4*)sB)[i]  = ((const float4*)g_B)[i];
        ((float4*)sCc)[i] = ((const float4*)g_Cc)[i];
    }
    if (tid < NOUT_) sBf[tid] = g_bf[tid];
    __syncthreads();

    int lane = tid & 31, wid = tid >> 5;

    float2 bo2  = ((const float2*)e_bo)[lane];
    float2 g1v  = ((const float2*)g1)[lane];
    float2 b1v  = ((const float2*)b1)[lane];
    float2 g2v  = ((const float2*)g2)[lane];
    float2 b2v  = ((const float2*)b2)[lane];
    float2 c2b2 = ((const float2*)c2b)[lane];
    u64 c2bp0 = pk2(c2b2.x, 0.f), c2bp1 = pk2(c2b2.y, 0.f);

    float* wcoW = sPW + wid * PWSC;   // [j][8]
    float* h1W  = wcoW + 224;         // 7 rows of 128

    float4 A4  = ((const float4*)sA)[lane];
    float4 B4  = ((const float4*)sB)[lane];
    float4 C4  = ((const float4*)sCc)[lane];

    const float* pC2 = sC2 + 4 * lane;

    int gw = blockIdx.x * NWARP + wid;
    for (int e = gw; e < BATCH_; e += totalWarps) {
        int myTok = 0;
        if (lane < 7) myTok = tokens[e * 7 + lane];
        int t[7];
        #pragma unroll
        for (int i = 0; i < 7; i++) t[i] = __shfl_sync(0xffffffffu, myTok, i);

        if (lane < 28) {
            int k = lane % 7;
            const float* eb = g_E + (lane * 6 + t[k]) * 42;
            float myw[7];
            float den = 0.f;
            #pragma unroll
            for (int q = 0; q < 7; q++) { float x = __ldg(eb + q * 6 + t[q]); myw[q] = x; den += x; }
            float inv = __fdividef(1.f, den);
            float4 wA = make_float4(myw[0] * inv, myw[1] * inv, myw[2] * inv, myw[3] * inv);
            float4 wB = make_float4(myw[4] * inv, myw[5] * inv, myw[6] * inv, 0.f);
            ((float4*)(wcoW + lane * 8))[0] = wA;
            ((float4*)(wcoW + lane * 8))[1] = wB;
        }
        __syncwarp();

        float2 y[7];
        float S[7][4];
        #pragma unroll
        for (int q = 0; q < 7; q++) {
            y[q] = bo2;
            S[q][0] = S[q][1] = S[q][2] = S[q][3] = 0.f;
        }
        #pragma unroll
        for (int j = 0; j < 28; j++) {
            int row = j * 6 + t[j % 7];
            float2 v  = ((const float2*)(sVW + row * 64))[lane];
            float4 pv = ((const float4*)(sP + row * 128))[lane];
            float4 wA = ((const float4*)(wcoW + j * 8))[0];
            float4 wB = ((const float4*)(wcoW + j * 8))[1];
            y[0].x = fmaf(wA.x, v.x, y[0].x); y[0].y = fmaf(wA.x, v.y, y[0].y);
            y[1].x = fmaf(wA.y, v.x, y[1].x); y[1].y = fmaf(wA.y, v.y, y[1].y);
            y[2].x = fmaf(wA.z, v.x, y[2].x); y[2].y = fmaf(wA.z, v.y, y[2].y);
            y[3].x = fmaf(wA.w, v.x, y[3].x); y[3].y = fmaf(wA.w, v.y, y[3].y);
            y[4].x = fmaf(wB.x, v.x, y[4].x); y[4].y = fmaf(wB.x, v.y, y[4].y);
            y[5].x = fmaf(wB.y, v.x, y[5].x); y[5].y = fmaf(wB.y, v.y, y[5].y);
            y[6].x = fmaf(wB.z, v.x, y[6].x); y[6].y = fmaf(wB.z, v.y, y[6].y);
            S[0][0] = fmaf(wA.x, pv.x, S[0][0]); S[0][1] = fmaf(wA.x, pv.y, S[0][1]);
            S[0][2] = fmaf(wA.x, pv.z, S[0][2]); S[0][3] = fmaf(wA.x, pv.w, S[0][3]);
            S[1][0] = fmaf(wA.y, pv.x, S[1][0]); S[1][1] = fmaf(wA.y, pv.y, S[1][1]);
            S[1][2] = fmaf(wA.y, pv.z, S[1][2]); S[1][3] = fmaf(wA.y, pv.w, S[1][3]);
            S[2][0] = fmaf(wA.z, pv.x, S[2][0]); S[2][1] = fmaf(wA.z, pv.y, S[2][1]);
            S[2][2] = fmaf(wA.z, pv.z, S[2][2]); S[2][3] = fmaf(wA.z, pv.w, S[2][3]);
            S[3][0] = fmaf(wA.w, pv.x, S[3][0]); S[3][1] = fmaf(wA.w, pv.y, S[3][1]);
            S[3][2] = fmaf(wA.w, pv.z, S[3][2]); S[3][3] = fmaf(wA.w, pv.w, S[3][3]);
            S[4][0] = fmaf(wB.x, pv.x, S[4][0]); S[4][1] = fmaf(wB.x, pv.y, S[4][1]);
            S[4][2] = fmaf(wB.x, pv.z, S[4][2]); S[4][3] = fmaf(wB.x, pv.w, S[4][3]);
            S[5][0] = fmaf(wB.y, pv.x, S[5][0]); S[5][1] = fmaf(wB.y, pv.y, S[5][1]);
            S[5][2] = fmaf(wB.y, pv.z, S[5][2]); S[5][3] = fmaf(wB.y, pv.w, S[5][3]);
            S[6][0] = fmaf(wB.z, pv.x, S[6][0]); S[6][1] = fmaf(wB.z, pv.y, S[6][1]);
            S[6][2] = fmaf(wB.z, pv.z, S[6][2]); S[6][3] = fmaf(wB.z, pv.w, S[6][3]);
        }

        float mu[7], rs[7];
        {
            float s1[7], ss1[7];
            #pragma unroll
            for (int q = 0; q < 7; q++) {
                s1[q]  = y[q].x + y[q].y;
                ss1[q] = y[q].x * y[q].x + y[q].y * y[q].y;
            }
            #pragma unroll
            for (int o = 16; o > 0; o >>= 1) {
                #pragma unroll
                for (int q = 0; q < 7; q++) {
                    s1[q]  += __shfl_xor_sync(0xffffffffu, s1[q], o);
                    ss1[q] += __shfl_xor_sync(0xffffffffu, ss1[q], o);
                }
            }
            #pragma unroll
            for (int q = 0; q < 7; q++) {
                mu[q] = s1[q] * (1.f / 64.f);
                float var = ss1[q] * (1.f / 64.f) - mu[q] * mu[q];
                rs[q] = rsqrtf(var + EPS_);
            }
        }

        #pragma unroll
        for (int q = 0; q < 7; q++) {
            float4 hv;
            hv.x = fmaf(rs[q], C4.x + S[q][0] - mu[q] * A4.x, B4.x);
            hv.y = fmaf(rs[q], C4.y + S[q][1] - mu[q] * A4.y, B4.y);
            hv.z = fmaf(rs[q], C4.z + S[q][2] - mu[q] * A4.z, B4.z);
            hv.w = fmaf(rs[q], C4.w + S[q][3] - mu[q] * A4.w, B4.w);
            hv.x = fmaxf(hv.x, 0.f); hv.y = fmaxf(hv.y, 0.f);
            hv.z = fmaxf(hv.z, 0.f); hv.w = fmaxf(hv.w, 0.f);
            ((float4*)(h1W + q * 128))[lane] = hv;
        }
        __syncwarp();

        u64 ac0[7], ac1[7];
        #pragma unroll
        for (int i = 0; i < 7; i++) { ac0[i] = c2bp0; ac1[i] = c2bp1; }
        #pragma unroll 2
        for (int kk2 = 0; kk2 < 32; kk2++) {
            ulonglong2 wa = *(const ulonglong2*)(pC2 + (2 * kk2) * 128);
            ulonglong2 wb = *(const ulonglong2*)(pC2 + (2 * kk2 + 1) * 128);
            #pragma unroll
            for (int i = 0; i < 7; i++) {
                ulonglong2 hp = ((const ulonglong2*)(h1W + i * 128))[kk2];
                fma2(ac0[i], hp.x, wa.x); fma2(ac1[i], hp.x, wa.y);
                fma2(ac0[i], hp.y, wb.x); fma2(ac1[i], hp.y, wb.y);
            }
        }

        float2 xs = make_float2(0.f, 0.f);
        {
            float s2[7], ss2[7];
            float2 z[7];
            #pragma unroll
            for (int i = 0; i < 7; i++) {
                float2 f0 = up2(ac0[i]);
                float2 f1 = up2(ac1[i]);
                float xnx = (y[i].x - mu[i]) * rs[i] * g1v.x + b1v.x;
                float xny = (y[i].y - mu[i]) * rs[i] * g1v.y + b1v.y;
                float zx = xnx + fmaxf(f0.x + f0.y, 0.f);
                float zy = xny + fmaxf(f1.x + f1.y, 0.f);
                z[i] = make_float2(zx, zy);
                s2[i] = zx + zy;
                ss2[i] = zx * zx + zy * zy;
            }
            #pragma unroll
            for (int o = 16; o > 0; o >>= 1) {
                #pragma unroll
                for (int i = 0; i < 7; i++) {
                    s2[i]  += __shfl_xor_sync(0xffffffffu, s2[i], o);
                    ss2[i] += __shfl_xor_sync(0xffffffffu, ss2[i], o);
                }
            }
            #pragma unroll
            for (int i = 0; i < 7; i++) {
                float mean = s2[i] * (1.f / 64.f);
                float var  = ss2[i] * (1.f / 64.f) - mean * mean;
                float rstd = rsqrtf(var + EPS_);
                xs.x += (z[i].x - mean) * rstd * g2v.x + b2v.x;
                xs.y += (z[i].y - mean) * rstd * g2v.y + b2v.y;
            }
        }
        __syncwarp();

        ((float2*)h1W)[lane] = xs;
        __syncwarp();
        if (lane < NOUT_) {
            const float4* wrow = (const float4*)(g_Wft + lane * 64);
            float o = sBf[lane];
            #pragma unroll
            for (int d4 = 0; d4 < 16; d4++) {
                float4 xv = ((const float4*)h1W)[d4];
                float4 wv = __ldg(wrow + d4);
                o = fmaf(xv.x, wv.x, o); o = fmaf(xv.y, wv.y, o);
                o = fmaf(xv.z, wv.z, o); o = fmaf(xv.w, wv.w, o);
            }
            out[e * NOUT_ + lane] = o;
        }
        __syncwarp();
    }
}

extern "C" void kernel_launch(void* const* d_in, const int* in_sizes, int n_in,
                              void* d_out, int out_size) {
    const int*   tokens = (const int*)d_in[0];
    const float* emb    = (const float*)d_in[1];
    const float* pos    = (const float*)d_in[2];
    // d_in[3] qparam unused (decoder softmax over singleton q axis == 1)
    const float* in_w   = (const float*)d_in[4];
    const float* in_b   = (const float*)d_in[5];
    const float* e_wq   = (const float*)d_in[6];
    const float* e_wk   = (const float*)d_in[7];
    const float* e_wv   = (const float*)d_in[8];
    const float* e_wo   = (const float*)d_in[9];
    const float* e_bo   = (const float*)d_in[10];
    const float* e_g1   = (const float*)d_in[11];
    const float* e_b1   = (const float*)d_in[12];
    const float* e_c1w  = (const float*)d_in[13];
    const float* e_c1b  = (const float*)d_in[14];
    const float* e_c2w  = (const float*)d_in[15];
    const float* e_c2b  = (const float*)d_in[16];
    const float* e_g2   = (const float*)d_in[17];
    const float* e_b2   = (const float*)d_in[18];
    // d_in[19] d_wq, d_in[20] d_wk unused
    const float* d_wv   = (const float*)d_in[21];
    const float* d_wo   = (const float*)d_in[22];
    const float* d_bo   = (const float*)d_in[23];
    const float* fc_w   = (const float*)d_in[24];
    const float* fc_b   = (const float*)d_in[25];
    float* out = (float*)d_out;

    kP1<<<48, 256>>>(emb, pos, in_w, in_b, e_wq, e_wk, e_wv);
    kP2<<<52, 256>>>(e_wo, d_wv, d_wo);
    kP3<<<18, 256>>>(e_g1, e_b1, e_c1w, e_c1b, e_bo, d_bo, fc_w, fc_b, e_c2w);

    int dev = 0;
    cudaGetDevice(&dev);
    int smCount = 148;
    cudaDeviceGetAttribute(&smCount, cudaDevAttrMultiProcessorCount, dev);

    size_t smemBytes = SMEM_FLOATS * sizeof(float);
    cudaFuncSetAttribute(k_main, cudaFuncAttributeMaxDynamicSharedMemorySize, (int)smemBytes);
    k_main<<<smCount, NTHR, smemBytes>>>(tokens, e_bo, e_g1, e_b1, e_c2b,
                                         e_g2, e_b2, out, smCount * NWARP);
}

// round 17
// speedup vs baseline: 1.6820x; 1.0794x over previous
#include <cuda_runtime.h>

#define H_ 4
#define D_ 64
#define L_ 7
#define VOCAB_ 6
#define NOUT_ 11
#define BATCH_ 32768
#define EPS_ 1e-5f

using u64 = unsigned long long;

__device__ __forceinline__ u64 pk2(float x, float y) {
    u64 r; asm("mov.b64 %0, {%1, %2};" : "=l"(r) : "f"(x), "f"(y)); return r;
}
__device__ __forceinline__ void fma2(u64& a, u64 x, u64 w) {
    asm("fma.rn.f32x2 %0, %1, %2, %0;" : "+l"(a) : "l"(x), "l"(w));
}
__device__ __forceinline__ float2 up2(u64 v) {
    float2 r; asm("mov.b64 {%0, %1}, %2;" : "=f"(r.x), "=f"(r.y) : "l"(v)); return r;
}

// ---------------- device scratch ----------------
__device__ float g_Q[168 * D_];
__device__ float g_K[168 * D_];
__device__ float g_V[168 * D_];
__device__ float g_Wd[D_ * D_];
__device__ float g_E[H_ * L_ * VOCAB_ * L_ * VOCAB_]; // [h][k][tk][q][tq] (LDG)
__device__ float g_VW[H_ * L_ * VOCAB_ * D_];         // [jt][64]
__device__ float g_P[168 * 128];                      // [jt][128] = VW[jt] @ (g1*C1)
__device__ float g_A[128];
__device__ float g_B[128];
__device__ float g_Cc[128];
__device__ float g_Wft[NOUT_ * D_];
__device__ float g_bf[NOUT_];
__device__ float g_C2p[64 * 128];                     // [kk][c][2]

// ---------------- prep kernel A: QKV (48) | Wd (16) | C2p (1) ----------------
__global__ void kA(const float* __restrict__ emb, const float* __restrict__ pos,
                   const float* __restrict__ in_w, const float* __restrict__ in_b,
                   const float* __restrict__ e_wq, const float* __restrict__ e_wk,
                   const float* __restrict__ e_wv,
                   const float* __restrict__ d_wv, const float* __restrict__ d_wo,
                   const float* __restrict__ c2w) {
    __shared__ float sT[11 * 64];
    int tid = threadIdx.x;
    int cta = blockIdx.x;

    if (cta < 48) {
        int combo = cta >> 2, s = cta & 3;
        int which = combo >> 2, h = combo & 3;
        int r0 = s * 11;
        int nr = (42 - r0) < 11 ? (42 - r0) : 11;

        for (int i = tid; i < nr * 64; i += 256) {
            int lvl = i >> 6, e = i & 63;
            int lv = r0 + lvl;
            int l = lv / 6, v = lv % 6;
            float acc = in_b[e];
            #pragma unroll 8
            for (int d = 0; d < 64; d++) acc = fmaf(emb[v * 64 + d], in_w[d * 64 + e], acc);
            acc = fmaf(pos[l], in_w[64 * 64 + e], acc);
            sT[i] = acc;
        }
        __syncthreads();

        const float* w = (which == 0) ? e_wq : (which == 1) ? e_wk : e_wv;
        float* outg = (which == 0) ? g_Q : (which == 1) ? g_K : g_V;
        for (int i = tid; i < nr * 64; i += 256) {
            int lvl = i >> 6, e = i & 63;
            float acc = 0.f;
            #pragma unroll 8
            for (int d = 0; d < 64; d++) acc = fmaf(sT[lvl * 64 + d], w[(h * 64 + d) * 64 + e], acc);
            outg[(h * 42 + r0 + lvl) * 64 + e] = acc;
        }
    } else if (cta < 64) {
        int idx = cta - 48;
        int r = idx * 4 + (tid >> 6);
        int j = tid & 63;
        float acc = 0.f;
        for (int hh = 0; hh < 4; hh++)
            #pragma unroll 8
            for (int d = 0; d < 64; d++)
                acc = fmaf(d_wv[(hh * 64 + r) * 64 + d], d_wo[(hh * 64 + d) * 64 + j], acc);
        g_Wd[r * 64 + j] = acc;
    } else {
        for (int i = tid; i < 64 * 128; i += 256) {
            int kk = i >> 7, rr = i & 127;
            int c = rr >> 1, jj = rr & 1;
            g_C2p[i] = c2w[(2 * kk + jj) * 64 + c];
        }
    }
}

// ---------------- prep kernel B: E (28) | VW (8) | P (16, local VW recompute) | ABCc | Wft ----------------
__global__ void kB(const float* __restrict__ e_wo,
                   const float* __restrict__ g1, const float* __restrict__ b1,
                   const float* __restrict__ c1w, const float* __restrict__ c1b,
                   const float* __restrict__ e_bo,
                   const float* __restrict__ d_bo,
                   const float* __restrict__ fc_w, const float* __restrict__ fc_b) {
    __shared__ float sG[64 * 128];    // g1[d]*C1[d][c]
    __shared__ float sVWl[11 * 64];   // local VW rows for P slice
    int tid = threadIdx.x;
    int cta = blockIdx.x;

    if (cta < 28) {
        int h = cta / 7, seg = cta % 7;
        for (int i = seg * 252 + tid; i < (seg + 1) * 252; i += 256) {
            int r = i;
            int tq = r % 6; r /= 6;
            int q  = r % 7; r /= 7;
            int tk = r % 6; r /= 6;
            int k  = r;
            const float* Q = g_Q + ((h * 7 + q) * 6 + tq) * 64;
            const float* K = g_K + ((h * 7 + k) * 6 + tk) * 64;
            float s = 0.f;
            #pragma unroll 8
            for (int d = 0; d < 64; d++) s = fmaf(Q[d], K[d], s);
            g_E[h * 1764 + i] = __expf(s * 0.125f);
        }
    } else if (cta < 36) {
        int idx = cta - 28;
        for (int i = tid; i < 21 * 64; i += 256) {
            int rl = i >> 6, e = i & 63;
            int row = idx * 21 + rl;
            int h = row / 42;
            float acc = 0.f;
            #pragma unroll 8
            for (int d = 0; d < 64; d++) acc = fmaf(g_V[row * 64 + d], e_wo[(h * 64 + d) * 64 + e], acc);
            g_VW[row * 64 + e] = acc;
        }
    } else if (cta < 52) {
        int idx = cta - 36;
        // stage sG
        for (int i = tid; i < 64 * 128; i += 256) {
            int d = i >> 7;
            sG[i] = g1[d] * c1w[i];
        }
        int i0 = idx * 1344, i1 = i0 + 1344;
        int r0 = i0 >> 7, r1 = (i1 - 1) >> 7;     // inclusive row range (<= 11 rows)
        // recompute needed VW rows locally (same reduction order as VW branch)
        for (int i = tid; i < (r1 - r0 + 1) * 64; i += 256) {
            int rl = i >> 6, e = i & 63;
            int row = r0 + rl;
            int h = row / 42;
            float acc = 0.f;
            #pragma unroll 8
            for (int d = 0; d < 64; d++) acc = fmaf(g_V[row * 64 + d], e_wo[(h * 64 + d) * 64 + e], acc);
            sVWl[i] = acc;
        }
        __syncthreads();
        for (int i = i0 + tid; i < i1; i += 256) {
            int row = i >> 7, c = i & 127;
            const float* vw = sVWl + (row - r0) * 64;
            float acc = 0.f;
            #pragma unroll 8
            for (int d = 0; d < 64; d++) acc = fmaf(vw[d], sG[d * 128 + c], acc);
            g_P[i] = acc;
        }
    } else if (cta == 52) {
        for (int i = tid; i < 64 * 128; i += 256) {
            int d = i >> 7;
            sG[i] = g1[d] * c1w[i];
        }
        __syncthreads();
        for (int c = tid; c < 128; c += 256) {
            float a = 0.f, b = c1b[c], cc = 0.f;
            #pragma unroll 8
            for (int d = 0; d < 64; d++) {
                float g = sG[d * 128 + c];
                a += g;
                b = fmaf(b1[d], c1w[d * 128 + c], b);
                cc = fmaf(e_bo[d], g, cc);
            }
            g_A[c] = a; g_B[c] = b; g_Cc[c] = cc;
        }
    } else {
        for (int i = tid; i < NOUT_ * 64; i += 256) {
            int n = i >> 6, d = i & 63;
            float acc = 0.f;
            #pragma unroll 8
            for (int j = 0; j < 64; j++) acc = fmaf(g_Wd[d * 64 + j], fc_w[j * NOUT_ + n], acc);
            g_Wft[i] = acc;
        }
        if (tid < NOUT_) {
            float b = fc_b[tid];
            #pragma unroll 8
            for (int j = 0; j < 64; j++) b = fmaf(d_bo[j], fc_w[j * NOUT_ + tid], b);
            g_bf[tid] = b;
        }
    }
}

// ---------------- main fused kernel (R13 configuration: 15 warps) ----------------
#define NWARP 15
#define NTHR  (NWARP * 32)
#define PWSC  1120
#define SMEM_FLOATS (40848 + NWARP * PWSC)

__global__ __launch_bounds__(NTHR, 1)
void k_main(const int* __restrict__ tokens,
            const float* __restrict__ e_bo,
            const float* __restrict__ g1, const float* __restrict__ b1,
            const float* __restrict__ c2b,
            const float* __restrict__ g2, const float* __restrict__ b2,
            float* __restrict__ out, int totalWarps) {
    extern __shared__ float sm[];
    float* sP   = sm;                 // 21504
    float* sVW  = sP + 21504;         // 10752
    float* sC2  = sVW + 10752;        // 8192
    float* sA   = sC2 + 8192;         // 128
    float* sB   = sA + 128;           // 128
    float* sCc  = sB + 128;           // 128
    float* sBf  = sCc + 128;          // 16
    float* sPW  = sBf + 16;

    int tid = threadIdx.x;
    for (int i = tid; i < 21504 / 4; i += NTHR) ((float4*)sP)[i]  = ((const float4*)g_P)[i];
    for (int i = tid; i < 10752 / 4; i += NTHR) ((float4*)sVW)[i] = ((const float4*)g_VW)[i];
    for (int i = tid; i < 8192 / 4;  i += NTHR) ((float4*)sC2)[i] = ((const float4*)g_C2p)[i];
    for (int i = tid; i < 128 / 4;   i += NTHR) {
        ((float4*)sA)[i]  = ((const float4*)g_A)[i];
        ((float4*)sB)[i]  = ((const float4*)g_B)[i];
        ((float4*)sCc)[i] = ((const float4*)g_Cc)[i];
    }
    if (tid < NOUT_) sBf[tid] = g_bf[tid];
    __syncthreads();

    int lane = tid & 31, wid = tid >> 5;

    float2 bo2  = ((const float2*)e_bo)[lane];
    float2 g1v  = ((const float2*)g1)[lane];
    float2 b1v  = ((const float2*)b1)[lane];
    float2 g2v  = ((const float2*)g2)[lane];
    float2 b2v  = ((const float2*)b2)[lane];
    float2 c2b2 = ((const float2*)c2b)[lane];
    u64 c2bp0 = pk2(c2b2.x, 0.f), c2bp1 = pk2(c2b2.y, 0.f);

    float* wcoW = sPW + wid * PWSC;   // [j][8]
    float* h1W  = wcoW + 224;         // 7 rows of 128

    float4 A4  = ((const float4*)sA)[lane];
    float4 B4  = ((const float4*)sB)[lane];
    float4 C4  = ((const float4*)sCc)[lane];

    const float* pC2 = sC2 + 4 * lane;

    int gw = blockIdx.x * NWARP + wid;
    for (int e = gw; e < BATCH_; e += totalWarps) {
        int myTok = 0;
        if (lane < 7) myTok = tokens[e * 7 + lane];
        int t[7];
        #pragma unroll
        for (int i = 0; i < 7; i++) t[i] = __shfl_sync(0xffffffffu, myTok, i);

        if (lane < 28) {
            int k = lane % 7;
            const float* eb = g_E + (lane * 6 + t[k]) * 42;
            float myw[7];
            float den = 0.f;
            #pragma unroll
            for (int q = 0; q < 7; q++) { float x = __ldg(eb + q * 6 + t[q]); myw[q] = x; den += x; }
            float inv = __fdividef(1.f, den);
            float4 wA = make_float4(myw[0] * inv, myw[1] * inv, myw[2] * inv, myw[3] * inv);
            float4 wB = make_float4(myw[4] * inv, myw[5] * inv, myw[6] * inv, 0.f);
            ((float4*)(wcoW + lane * 8))[0] = wA;
            ((float4*)(wcoW + lane * 8))[1] = wB;
        }
        __syncwarp();

        float2 y[7];
        float S[7][4];
        #pragma unroll
        for (int q = 0; q < 7; q++) {
            y[q] = bo2;
            S[q][0] = S[q][1] = S[q][2] = S[q][3] = 0.f;
        }
        #pragma unroll
        for (int j = 0; j < 28; j++) {
            int row = j * 6 + t[j % 7];
            float2 v  = ((const float2*)(sVW + row * 64))[lane];
            float4 pv = ((const float4*)(sP + row * 128))[lane];
            float4 wA = ((const float4*)(wcoW + j * 8))[0];
            float4 wB = ((const float4*)(wcoW + j * 8))[1];
            y[0].x = fmaf(wA.x, v.x, y[0].x); y[0].y = fmaf(wA.x, v.y, y[0].y);
            y[1].x = fmaf(wA.y, v.x, y[1].x); y[1].y = fmaf(wA.y, v.y, y[1].y);
            y[2].x = fmaf(wA.z, v.x, y[2].x); y[2].y = fmaf(wA.z, v.y, y[2].y);
            y[3].x = fmaf(wA.w, v.x, y[3].x); y[3].y = fmaf(wA.w, v.y, y[3].y);
            y[4].x = fmaf(wB.x, v.x, y[4].x); y[4].y = fmaf(wB.x, v.y, y[4].y);
            y[5].x = fmaf(wB.y, v.x, y[5].x); y[5].y = fmaf(wB.y, v.y, y[5].y);
            y[6].x = fmaf(wB.z, v.x, y[6].x); y[6].y = fmaf(wB.z, v.y, y[6].y);
            S[0][0] = fmaf(wA.x, pv.x, S[0][0]); S[0][1] = fmaf(wA.x, pv.y, S[0][1]);
            S[0][2] = fmaf(wA.x, pv.z, S[0][2]); S[0][3] = fmaf(wA.x, pv.w, S[0][3]);
            S[1][0] = fmaf(wA.y, pv.x, S[1][0]); S[1][1] = fmaf(wA.y, pv.y, S[1][1]);
            S[1][2] = fmaf(wA.y, pv.z, S[1][2]); S[1][3] = fmaf(wA.y, pv.w, S[1][3]);
            S[2][0] = fmaf(wA.z, pv.x, S[2][0]); S[2][1] = fmaf(wA.z, pv.y, S[2][1]);
            S[2][2] = fmaf(wA.z, pv.z, S[2][2]); S[2][3] = fmaf(wA.z, pv.w, S[2][3]);
            S[3][0] = fmaf(wA.w, pv.x, S[3][0]); S[3][1] = fmaf(wA.w, pv.y, S[3][1]);
            S[3][2] = fmaf(wA.w, pv.z, S[3][2]); S[3][3] = fmaf(wA.w, pv.w, S[3][3]);
            S[4][0] = fmaf(wB.x, pv.x, S[4][0]); S[4][1] = fmaf(wB.x, pv.y, S[4][1]);
            S[4][2] = fmaf(wB.x, pv.z, S[4][2]); S[4][3] = fmaf(wB.x, pv.w, S[4][3]);
            S[5][0] = fmaf(wB.y, pv.x, S[5][0]); S[5][1] = fmaf(wB.y, pv.y, S[5][1]);
            S[5][2] = fmaf(wB.y, pv.z, S[5][2]); S[5][3] = fmaf(wB.y, pv.w, S[5][3]);
            S[6][0] = fmaf(wB.z, pv.x, S[6][0]); S[6][1] = fmaf(wB.z, pv.y, S[6][1]);
            S[6][2] = fmaf(wB.z, pv.z, S[6][2]); S[6][3] = fmaf(wB.z, pv.w, S[6][3]);
        }

        float mu[7], rs[7];
        {
            float s1[7], ss1[7];
            #pragma unroll
            for (int q = 0; q < 7; q++) {
                s1[q]  = y[q].x + y[q].y;
                ss1[q] = y[q].x * y[q].x + y[q].y * y[q].y;
            }
            #pragma unroll
            for (int o = 16; o > 0; o >>= 1) {
                #pragma unroll
                for (int q = 0; q < 7; q++) {
                    s1[q]  += __shfl_xor_sync(0xffffffffu, s1[q], o);
                    ss1[q] += __shfl_xor_sync(0xffffffffu, ss1[q], o);
                }
            }
            #pragma unroll
            for (int q = 0; q < 7; q++) {
                mu[q] = s1[q] * (1.f / 64.f);
                float var = ss1[q] * (1.f / 64.f) - mu[q] * mu[q];
                rs[q] = rsqrtf(var + EPS_);
            }
        }

        #pragma unroll
        for (int q = 0; q < 7; q++) {
            float4 hv;
            hv.x = fmaf(rs[q], C4.x + S[q][0] - mu[q] * A4.x, B4.x);
            hv.y = fmaf(rs[q], C4.y + S[q][1] - mu[q] * A4.y, B4.y);
            hv.z = fmaf(rs[q], C4.z + S[q][2] - mu[q] * A4.z, B4.z);
            hv.w = fmaf(rs[q], C4.w + S[q][3] - mu[q] * A4.w, B4.w);
            hv.x = fmaxf(hv.x, 0.f); hv.y = fmaxf(hv.y, 0.f);
            hv.z = fmaxf(hv.z, 0.f); hv.w = fmaxf(hv.w, 0.f);
            ((float4*)(h1W + q * 128))[lane] = hv;
        }
        __syncwarp();

        u64 ac0[7], ac1[7];
        #pragma unroll
        for (int i = 0; i < 7; i++) { ac0[i] = c2bp0; ac1[i] = c2bp1; }
        #pragma unroll 2
        for (int kk2 = 0; kk2 < 32; kk2++) {
            ulonglong2 wa = *(const ulonglong2*)(pC2 + (2 * kk2) * 128);
            ulonglong2 wb = *(const ulonglong2*)(pC2 + (2 * kk2 + 1) * 128);
            #pragma unroll
            for (int i = 0; i < 7; i++) {
                ulonglong2 hp = ((const ulonglong2*)(h1W + i * 128))[kk2];
                fma2(ac0[i], hp.x, wa.x); fma2(ac1[i], hp.x, wa.y);
                fma2(ac0[i], hp.y, wb.x); fma2(ac1[i], hp.y, wb.y);
            }
        }

        float2 xs = make_float2(0.f, 0.f);
        {
            float s2[7], ss2[7];
            float2 z[7];
            #pragma unroll
            for (int i = 0; i < 7; i++) {
                float2 f0 = up2(ac0[i]);
                float2 f1 = up2(ac1[i]);
                float xnx = (y[i].x - mu[i]) * rs[i] * g1v.x + b1v.x;
                float xny = (y[i].y - mu[i]) * rs[i] * g1v.y + b1v.y;
                float zx = xnx + fmaxf(f0.x + f0.y, 0.f);
                float zy = xny + fmaxf(f1.x + f1.y, 0.f);
                z[i] = make_float2(zx, zy);
                s2[i] = zx + zy;
                ss2[i] = zx * zx + zy * zy;
            }
            #pragma unroll
            for (int o = 16; o > 0; o >>= 1) {
                #pragma unroll
                for (int i = 0; i < 7; i++) {
                    s2[i]  += __shfl_xor_sync(0xffffffffu, s2[i], o);
                    ss2[i] += __shfl_xor_sync(0xffffffffu, ss2[i], o);
                }
            }
            #pragma unroll
            for (int i = 0; i < 7; i++) {
                float mean = s2[i] * (1.f / 64.f);
                float var  = ss2[i] * (1.f / 64.f) - mean * mean;
                float rstd = rsqrtf(var + EPS_);
                xs.x += (z[i].x - mean) * rstd * g2v.x + b2v.x;
                xs.y += (z[i].y - mean) * rstd * g2v.y + b2v.y;
            }
        }
        __syncwarp();

        ((float2*)h1W)[lane] = xs;
        __syncwarp();
        if (lane < NOUT_) {
            const float4* wrow = (const float4*)(g_Wft + lane * 64);
            float o = sBf[lane];
            #pragma unroll
            for (int d4 = 0; d4 < 16; d4++) {
                float4 xv = ((const float4*)h1W)[d4];
                float4 wv = __ldg(wrow + d4);
                o = fmaf(xv.x, wv.x, o); o = fmaf(xv.y, wv.y, o);
                o = fmaf(xv.z, wv.z, o); o = fmaf(xv.w, wv.w, o);
            }
            out[e * NOUT_ + lane] = o;
        }
        __syncwarp();
    }
}

extern "C" void kernel_launch(void* const* d_in, const int* in_sizes, int n_in,
                              void* d_out, int out_size) {
    const int*   tokens = (const int*)d_in[0];
    const float* emb    = (const float*)d_in[1];
    const float* pos    = (const float*)d_in[2];
    // d_in[3] qparam unused (decoder softmax over singleton q axis == 1)
    const float* in_w   = (const float*)d_in[4];
    const float* in_b   = (const float*)d_in[5];
    const float* e_wq   = (const float*)d_in[6];
    const float* e_wk   = (const float*)d_in[7];
    const float* e_wv   = (const float*)d_in[8];
    const float* e_wo   = (const float*)d_in[9];
    const float* e_bo   = (const float*)d_in[10];
    const float* e_g1   = (const float*)d_in[11];
    const float* e_b1   = (const float*)d_in[12];
    const float* e_c1w  = (const float*)d_in[13];
    const float* e_c1b  = (const float*)d_in[14];
    const float* e_c2w  = (const float*)d_in[15];
    const float* e_c2b  = (const float*)d_in[16];
    const float* e_g2   = (const float*)d_in[17];
    const float* e_b2   = (const float*)d_in[18];
    // d_in[19] d_wq, d_in[20] d_wk unused
    const float* d_wv   = (const float*)d_in[21];
    const float* d_wo   = (const float*)d_in[22];
    const float* d_bo   = (const float*)d_in[23];
    const float* fc_w   = (const float*)d_in[24];
    const float* fc_b   = (const float*)d_in[25];
    float* out = (float*)d_out;

    kA<<<65, 256>>>(emb, pos, in_w, in_b, e_wq, e_wk, e_wv, d_wv, d_wo, e_c2w);
    kB<<<54, 256>>>(e_wo, e_g1, e_b1, e_c1w, e_c1b, e_bo, d_bo, fc_w, fc_b);

    int dev = 0;
    cudaGetDevice(&dev);
    int smCount = 148;
    cudaDeviceGetAttribute(&smCount, cudaDevAttrMultiProcessorCount, dev);

    size_t smemBytes = SMEM_FLOATS * sizeof(float);
    cudaFuncSetAttribute(k_main, cudaFuncAttributeMaxDynamicSharedMemorySize, (int)smemBytes);
    k_main<<<smCount, NTHR, smemBytes>>>(tokens, e_bo, e_g1, e_b1, e_c2b,
                                         e_g2, e_b2, out, smCount * NWARP);
}